// round 6
// baseline (speedup 1.0000x reference)
#include <cuda_runtime.h>
#include <math.h>

#define BB 2
#define MM 4096
#define CC 256
#define HW 64
#define NBINS 512
#define QCAP 96
#define NPOS_MAX 169
#define PQS 36                    // 32-ch slice stride (floats)
#define ASTR 260
#define DSTR 172
#define PW0 73
#define TOTPOS 7924               // 73^2 + 41^2 + 25^2 + 17^2

__device__ __align__(1024) float g_pyr2[BB * TOTPOS * 256];
__device__ int g_cnt[NBINS];
__device__ int g_qlist[NBINS * QCAP];

__constant__ int c_lvl_base[4] = {0, 5329, 7010, 7635};
__constant__ int c_lvl_pw[4]   = {73, 41, 25, 17};

__device__ __forceinline__ void fma2(unsigned long long& d, unsigned long long a,
                                     unsigned long long b) {
    asm("fma.rn.f32x2 %0, %1, %2, %0;" : "+l"(d) : "l"(a), "l"(b));
}
__device__ __forceinline__ float unpack_sum(unsigned long long v) {
    return __uint_as_float((unsigned)v) + __uint_as_float((unsigned)(v >> 32));
}
__device__ __forceinline__ void bulkcp(unsigned dst, const void* src,
                                       unsigned bytes, unsigned mbar) {
    asm volatile("cp.async.bulk.shared::cluster.global.mbarrier::complete_tx::bytes "
                 "[%0], [%1], %2, [%3];" :: "r"(dst), "l"(src), "r"(bytes), "r"(mbar)
                 : "memory");
}
__device__ __forceinline__ void mbar_init(unsigned mbar, unsigned cnt) {
    asm volatile("mbarrier.init.shared.b64 [%0], %1;" :: "r"(mbar), "r"(cnt) : "memory");
}
__device__ __forceinline__ void mbar_expect(unsigned mbar, unsigned bytes) {
    asm volatile("mbarrier.arrive.expect_tx.shared.b64 _, [%0], %1;"
                 :: "r"(mbar), "r"(bytes) : "memory");
}
__device__ __forceinline__ void mbar_wait(unsigned mbar, unsigned parity) {
    unsigned done;
    asm volatile("{\n\t.reg .pred p;\n\t"
                 "mbarrier.try_wait.parity.shared.b64 p, [%1], %2;\n\t"
                 "selp.b32 %0, 1, 0, p;\n\t}" : "=r"(done) : "r"(mbar), "r"(parity)
                 : "memory");
    while (!done)
        asm volatile("{\n\t.reg .pred p;\n\t"
                     "mbarrier.try_wait.parity.shared.b64 p, [%1], %2, 0x989680;\n\t"
                     "selp.b32 %0, 1, 0, p;\n\t}" : "=r"(done)
                     : "r"(mbar), "r"(parity) : "memory");
}

// ---------------- pre-kernels -----------------------------------------------
__global__ void zero_pyr_kernel() {
    float4* p = (float4*)g_pyr2;
    int n = BB * TOTPOS * 64;
    for (int i = blockIdx.x * blockDim.x + threadIdx.x; i < n;
         i += gridDim.x * blockDim.x)
        p[i] = make_float4(0.f, 0.f, 0.f, 0.f);
}

__global__ void transpose_kernel(const float* __restrict__ f2) {
    __shared__ float tile[32][33];
    int b = blockIdx.z, p0 = blockIdx.x * 32, c0 = blockIdx.y * 32;
    int tx = threadIdx.x, ty = threadIdx.y;
    tile[ty][tx] = f2[((size_t)b * CC + (c0 + ty)) * (HW * HW) + p0 + tx];
    __syncthreads();
    int p = p0 + ty, y = p >> 6, x = p & 63;
    int pos = (y + 4) * PW0 + (x + 4);
    g_pyr2[((size_t)b * TOTPOS + pos) * 256 + c0 + tx] = tile[tx][ty];
}

// all pooled levels straight from L0 (pooling is linear: mean over 2^l block)
__global__ void pool_all_kernel() {
    int r = blockIdx.x;
    int b = r / 1344, t = r - b * 1344;
    int l, W, i;
    if (t < 1024)      { l = 1; W = 32; i = t; }
    else if (t < 1280) { l = 2; W = 16; i = t - 1024; }
    else               { l = 3; W = 8;  i = t - 1280; }
    int y = i / W, x = i - (i / W) * W;
    int S = 1 << l;
    int c = threadIdx.x;
    const float* in = g_pyr2 + (size_t)b * TOTPOS * 256 + c;
    float s = 0.f;
    for (int dy = 0; dy < S; dy++)
        for (int dx = 0; dx < S; dx++)
            s += in[(size_t)((y * S + dy + 4) * PW0 + (x * S + dx + 4)) * 256];
    g_pyr2[((size_t)b * TOTPOS + c_lvl_base[l] + (y + 4) * c_lvl_pw[l] + (x + 4)) * 256 + c]
        = s / (float)(S * S);
}

__global__ void zero_cnt_kernel() {
    if (threadIdx.x < NBINS) g_cnt[threadIdx.x] = 0;
}

__global__ void hist_kernel(const float* __restrict__ cen) {
    int t = blockIdx.x * blockDim.x + threadIdx.x;
    if (t >= BB * MM) return;
    float cx = cen[2 * t], cy = cen[2 * t + 1];
    int bx = ((int)cx) >> 2;  bx = bx < 0 ? 0 : (bx > 15 ? 15 : bx);
    int by = ((int)cy) >> 2;  by = by < 0 ? 0 : (by > 15 ? 15 : by);
    int b = t / MM, m = t - b * MM;
    int bin = (b << 8) | (by << 4) | bx;
    int pos = atomicAdd(&g_cnt[bin], 1);
    if (pos < QCAP) g_qlist[bin * QCAP + pos] = m;
}

// ---------------- main kernel ------------------------------------------------
template <int NQI>
__device__ __forceinline__ void gemm_slice(const float* __restrict__ As,
                                           const float* __restrict__ Ps,
                                           int arow0, int s, const int* pidx,
                                           unsigned long long acc[4][8]) {
    #pragma unroll
    for (int c = 0; c < 32; c += 4) {
        ulonglong2 p[8];
        #pragma unroll
        for (int pi = 0; pi < 8; pi++)
            p[pi] = *(const ulonglong2*)&Ps[pidx[pi] * PQS + c];
        #pragma unroll
        for (int qi = 0; qi < NQI; qi++) {
            ulonglong2 a = *(const ulonglong2*)&As[(arow0 + 4 * qi) * ASTR + 32 * s + c];
            #pragma unroll
            for (int pi = 0; pi < 8; pi++) {
                fma2(acc[qi][pi], a.x, p[pi].x);
                fma2(acc[qi][pi], a.y, p[pi].y);
            }
        }
    }
}

__global__ __launch_bounds__(256, 2) void corr_kernel(const float* __restrict__ f1,
                                                      const float* __restrict__ cen,
                                                      float* __restrict__ out) {
    extern __shared__ float sm[];
    float* Ps0 = sm;                          // 169*36
    float* Ps1 = sm + NPOS_MAX * PQS;
    float* As  = sm + 2 * NPOS_MAX * PQS;     // 32*260
    float* Ds  = As + 32 * ASTR;              // 32*172
    __shared__ __align__(8) unsigned long long mb[3];

    int blk = blockIdx.x;
    int lvl = blk & 3, bin = blk >> 2;
    int b = bin >> 8, by = (bin >> 4) & 15, bx = bin & 15;
    int nq = g_cnt[bin]; if (nq > QCAP) nq = QCAP;
    if (nq == 0) return;

    int ixmin = (4 * bx) >> lvl, ixmax = (4 * bx + 3) >> lvl;
    int iymin = (4 * by) >> lvl, iymax = (4 * by + 3) >> lvl;
    int px0 = ixmin - 4, py0 = iymin - 4;
    int pw = ixmax - ixmin + 10, ph = iymax - iymin + 10;
    int Npos = pw * ph;
    int pwp = c_lvl_pw[lvl];

    int tid = threadIdx.x, lane = tid & 31, w = tid >> 5;
    int wq = w >> 2, wp = w & 3;
    int qsel = lane >> 3, psel = lane & 7;
    int arow0 = 16 * wq + qsel;
    bool posact = 64 * wp < Npos;
    float scale = 1.0f / (float)(1 << lvl);

    unsigned P0b = (unsigned)__cvta_generic_to_shared(Ps0);
    unsigned P1b = (unsigned)__cvta_generic_to_shared(Ps1);
    unsigned Ab  = (unsigned)__cvta_generic_to_shared(As);
    unsigned mbP[2] = {(unsigned)__cvta_generic_to_shared(&mb[0]),
                       (unsigned)__cvta_generic_to_shared(&mb[1])};
    unsigned mbA = (unsigned)__cvta_generic_to_shared(&mb[2]);
    unsigned Pb[2] = {P0b, P1b};

    if (tid == 0) { mbar_init(mbP[0], 1); mbar_init(mbP[1], 1); mbar_init(mbA, 1); }
    __syncthreads();
    int parP[2] = {0, 0}, parA = 0;

    int pidx[8];
    #pragma unroll
    for (int pi = 0; pi < 8; pi++) {
        int p = 64 * wp + psel + 8 * pi;
        pidx[pi] = p < Npos ? p : (Npos - 1);
    }

    const float* pbase = g_pyr2
        + ((size_t)b * TOTPOS + c_lvl_base[lvl] + (size_t)(py0 + 4) * pwp + (px0 + 4)) * 256;

    int nchunks = (nq + 31) >> 5;
    for (int ch = 0; ch < nchunks; ch++) {
        int qcnt = nq - 32 * ch; if (qcnt > 32) qcnt = 32;

        // issue A + first two P slices
        if (tid == 0) mbar_expect(mbA, (unsigned)qcnt * 1024u);
        if (tid < qcnt) {
            int m = g_qlist[bin * QCAP + 32 * ch + tid];
            bulkcp(Ab + (unsigned)tid * (ASTR * 4), f1 + ((size_t)b * MM + m) * CC,
                   1024u, mbA);
        }
        #pragma unroll
        for (int s0 = 0; s0 < 2; s0++) {
            if (tid == 0) mbar_expect(mbP[s0], (unsigned)Npos * 128u);
            for (int i = tid; i < Npos; i += 256) {
                int ly = i / pw, lx = i - (i / pw) * pw;
                bulkcp(Pb[s0] + (unsigned)i * (PQS * 4),
                       pbase + ((size_t)ly * pwp + lx) * 256 + s0 * 32, 128u, mbP[s0]);
            }
        }

        int rem = qcnt - 16 * wq;
        int nqi = rem <= 0 ? 0 : (rem >= 16 ? 4 : ((rem + 3) >> 2));

        unsigned long long acc[4][8];
        #pragma unroll
        for (int qi = 0; qi < 4; qi++)
            #pragma unroll
            for (int pi = 0; pi < 8; pi++) acc[qi][pi] = 0ull;

        mbar_wait(mbA, parA & 1); parA++;

        for (int s = 0; s < 8; s++) {
            int buf = s & 1;
            mbar_wait(mbP[buf], parP[buf] & 1); parP[buf]++;
            const float* Psb = buf ? Ps1 : Ps0;
            if (posact) {
                switch (nqi) {
                    case 4: gemm_slice<4>(As, Psb, arow0, s, pidx, acc); break;
                    case 3: gemm_slice<3>(As, Psb, arow0, s, pidx, acc); break;
                    case 2: gemm_slice<2>(As, Psb, arow0, s, pidx, acc); break;
                    case 1: gemm_slice<1>(As, Psb, arow0, s, pidx, acc); break;
                    default: break;
                }
            }
            __syncthreads();           // all warps done reading buf
            if (s < 6) {               // stage slice s+2 into this buf
                if (tid == 0) mbar_expect(mbP[buf], (unsigned)Npos * 128u);
                for (int i = tid; i < Npos; i += 256) {
                    int ly = i / pw, lx = i - (i / pw) * pw;
                    bulkcp(Pb[buf] + (unsigned)i * (PQS * 4),
                           pbase + ((size_t)ly * pwp + lx) * 256 + (s + 2) * 32,
                           128u, mbP[buf]);
                }
            }
        }

        // ---- dump D --------------------------------------------------------
        if (posact) {
            #pragma unroll
            for (int qi = 0; qi < 4; qi++)
                #pragma unroll
                for (int pi = 0; pi < 8; pi++) {
                    int p = 64 * wp + psel + 8 * pi;
                    if (p < Npos)
                        Ds[(16 * wq + qsel + 4 * qi) * DSTR + p] = unpack_sum(acc[qi][pi]);
                }
        }
        __syncthreads();

        // ---- bilinear epilogue --------------------------------------------
        for (int qq = w; qq < qcnt; qq += 8) {
            int m = g_qlist[bin * QCAP + 32 * ch + qq];
            float cx = cen[((size_t)b * MM + m) * 2 + 0];
            float cy = cen[((size_t)b * MM + m) * 2 + 1];
            float sx = cx * scale, sy = cy * scale;
            float fix = floorf(sx), fiy = floorf(sy);
            float fx = sx - fix, fy = sy - fiy;
            int ox = (int)fix - 4 - px0;
            int oy = (int)fiy - 4 - py0;
            float wx1 = fx, wx0 = 1.f - fx, wy1 = fy, wy0 = 1.f - fy;
            const float* Dq = Ds + qq * DSTR;
            for (int e = lane; e < 81; e += 32) {
                int i = e / 9, j = e - (e / 9) * 9;
                int base = (oy + j) * pw + (ox + i);
                float d00 = Dq[base],      d01 = Dq[base + 1];
                float d10 = Dq[base + pw], d11 = Dq[base + pw + 1];
                float val = wy0 * (wx0 * d00 + wx1 * d01)
                          + wy1 * (wx0 * d10 + wx1 * d11);
                out[((size_t)b * 324 + lvl * 81 + e) * MM + m] = val;
            }
        }
        __syncthreads();   // Ds/As reused by next chunk
    }
}

// ---------------- launch ----------------------------------------------------
extern "C" void kernel_launch(void* const* d_in, const int* in_sizes, int n_in,
                              void* d_out, int out_size) {
    const float* f1  = (const float*)d_in[0];
    const float* f2  = (const float*)d_in[1];
    const float* cen = (const float*)d_in[2];
    float* out = (float*)d_out;

    size_t smem = (size_t)(2 * NPOS_MAX * PQS + 32 * ASTR + 32 * DSTR) * sizeof(float);
    cudaFuncSetAttribute(corr_kernel, cudaFuncAttributeMaxDynamicSharedMemorySize,
                         (int)smem);

    zero_pyr_kernel<<<1024, 256>>>();
    transpose_kernel<<<dim3(HW * HW / 32, CC / 32, BB), dim3(32, 32)>>>(f2);
    pool_all_kernel<<<BB * 1344, 256>>>();
    zero_cnt_kernel<<<1, 512>>>();
    hist_kernel<<<(BB * MM + 255) / 256, 256>>>(cen);
    corr_kernel<<<NBINS * 4, 256, smem>>>(f1, cen, out);
}

// round 7
// speedup vs baseline: 1.4852x; 1.4852x over previous
#include <cuda_runtime.h>
#include <math.h>

#define BB 2
#define MM 4096
#define CC 256
#define HW 64
#define NBINS 512
#define QCAP 96
#define NPOS_MAX 169
#define PSTRH 132                 // padded half-row stride (floats)
#define DSTR 172
#define PW0 73
#define TOTPOS 7924               // 73^2 + 41^2 + 25^2 + 17^2

// layout: [b][h][pos][128]  (h = channel half)
__device__ __align__(1024) float g_pyr2[BB * 2 * TOTPOS * 128];
__device__ int g_cnt[NBINS];
__device__ int g_qlist[NBINS * QCAP];

__constant__ int c_lvl_base[4] = {0, 5329, 7010, 7635};
__constant__ int c_lvl_pw[4]   = {73, 41, 25, 17};

// ---------------- helpers ---------------------------------------------------
__device__ __forceinline__ void fma2(unsigned long long& d, unsigned long long a,
                                     unsigned long long b) {
    asm("fma.rn.f32x2 %0, %1, %2, %0;" : "+l"(d) : "l"(a), "l"(b));
}
__device__ __forceinline__ float unpack_sum(unsigned long long v) {
    return __uint_as_float((unsigned)v) + __uint_as_float((unsigned)(v >> 32));
}
__device__ __forceinline__ void bulkcp(unsigned dst, const void* src,
                                       unsigned bytes, unsigned mbar) {
    asm volatile("cp.async.bulk.shared::cluster.global.mbarrier::complete_tx::bytes "
                 "[%0], [%1], %2, [%3];" :: "r"(dst), "l"(src), "r"(bytes), "r"(mbar)
                 : "memory");
}
__device__ __forceinline__ void mbar_init(unsigned mbar, unsigned cnt) {
    asm volatile("mbarrier.init.shared.b64 [%0], %1;" :: "r"(mbar), "r"(cnt) : "memory");
}
__device__ __forceinline__ void mbar_expect(unsigned mbar, unsigned bytes) {
    asm volatile("mbarrier.arrive.expect_tx.shared.b64 _, [%0], %1;"
                 :: "r"(mbar), "r"(bytes) : "memory");
}
__device__ __forceinline__ void mbar_wait(unsigned mbar, unsigned parity) {
    unsigned done;
    asm volatile("{\n\t.reg .pred p;\n\t"
                 "mbarrier.try_wait.parity.shared.b64 p, [%1], %2;\n\t"
                 "selp.b32 %0, 1, 0, p;\n\t}" : "=r"(done) : "r"(mbar), "r"(parity)
                 : "memory");
    while (!done)
        asm volatile("{\n\t.reg .pred p;\n\t"
                     "mbarrier.try_wait.parity.shared.b64 p, [%1], %2, 0x989680;\n\t"
                     "selp.b32 %0, 1, 0, p;\n\t}" : "=r"(done)
                     : "r"(mbar), "r"(parity) : "memory");
}

// ---------------- kernel 1: transpose + zero counters -----------------------
__global__ void transpose_kernel(const float* __restrict__ f2) {
    __shared__ float tile[32][33];
    int b = blockIdx.z, p0 = blockIdx.x * 32, c0 = blockIdx.y * 32;
    int tx = threadIdx.x, ty = threadIdx.y;
    if (blockIdx.x == 0 && blockIdx.y == 0 && blockIdx.z == 0) {
        int t = ty * 32 + tx;
        if (t < NBINS) g_cnt[t] = 0;
    }
    tile[ty][tx] = f2[((size_t)b * CC + (c0 + ty)) * (HW * HW) + p0 + tx];
    __syncthreads();
    int p = p0 + ty, y = p >> 6, x = p & 63;
    int c = c0 + tx, h = c >> 7, cc = c & 127;
    int pos = (y + 4) * PW0 + (x + 4);
    g_pyr2[((size_t)(b * 2 + h) * TOTPOS + pos) * 128 + cc] = tile[tx][ty];
}

// ---------------- kernel 2: all pooled levels from L0 (pooling is linear) ---
__global__ void pool_all_kernel() {
    int r = blockIdx.x;
    int b = r / 1344, t = r - b * 1344;
    int l, W, i;
    if (t < 1024)      { l = 1; W = 32; i = t; }
    else if (t < 1280) { l = 2; W = 16; i = t - 1024; }
    else               { l = 3; W = 8;  i = t - 1280; }
    int y = i / W, x = i - (i / W) * W;
    int S = 1 << l;
    int c = threadIdx.x;                 // 256 = full channel
    int h = c >> 7, cc = c & 127;
    const float* in = g_pyr2 + (size_t)(b * 2 + h) * TOTPOS * 128 + cc;
    float s = 0.f;
    for (int dy = 0; dy < S; dy++)
        for (int dx = 0; dx < S; dx++)
            s += in[(size_t)((y * S + dy + 4) * PW0 + (x * S + dx + 4)) * 128];
    g_pyr2[((size_t)(b * 2 + h) * TOTPOS + c_lvl_base[l]
            + (y + 4) * c_lvl_pw[l] + (x + 4)) * 128 + cc] = s / (float)(S * S);
}

// ---------------- kernel 3: histogram + halo zeroing ------------------------
__global__ void hist_kernel(const float* __restrict__ cen) {
    int t = blockIdx.x * blockDim.x + threadIdx.x;

    // zero the halo positions of every level (both channel halves)
    for (int p = t; p < BB * 2 * TOTPOS; p += 32 * 256) {
        int pp = p % TOTPOS;
        int l = pp < 5329 ? 0 : (pp < 7010 ? 1 : (pp < 7635 ? 2 : 3));
        int pwl = c_lvl_pw[l];
        int r = pp - c_lvl_base[l];
        int y = r / pwl, x = r - (r / pwl) * pwl;
        int W = pwl - 9;
        if (x < 4 || x >= W + 4 || y < 4 || y >= W + 4) {
            float4* dst = (float4*)(g_pyr2 + (size_t)p * 128);
            #pragma unroll 4
            for (int i = 0; i < 32; i++) dst[i] = make_float4(0.f, 0.f, 0.f, 0.f);
        }
    }

    if (t < BB * MM) {
        float cx = cen[2 * t], cy = cen[2 * t + 1];
        int bx = ((int)cx) >> 2;  bx = bx < 0 ? 0 : (bx > 15 ? 15 : bx);
        int by = ((int)cy) >> 2;  by = by < 0 ? 0 : (by > 15 ? 15 : by);
        int b = t / MM, m = t - b * MM;
        int bin = (b << 8) | (by << 4) | bx;
        int pos = atomicAdd(&g_cnt[bin], 1);
        if (pos < QCAP) g_qlist[bin * QCAP + pos] = m;
    }
}

// ---------------- main kernel ------------------------------------------------
template <int NQI>
__device__ __forceinline__ void gemm_half(const float* __restrict__ As,
                                          const float* __restrict__ Ps,
                                          int qsel, const int* pidx,
                                          unsigned long long acc[4][4]) {
    #pragma unroll 2
    for (int c = 0; c < 128; c += 4) {
        ulonglong2 a[NQI], p[4];
        #pragma unroll
        for (int qi = 0; qi < NQI; qi++)
            a[qi] = *(const ulonglong2*)&As[(qsel + 4 * qi) * PSTRH + c];
        #pragma unroll
        for (int pi = 0; pi < 4; pi++)
            p[pi] = *(const ulonglong2*)&Ps[pidx[pi] * PSTRH + c];
        #pragma unroll
        for (int qi = 0; qi < NQI; qi++)
            #pragma unroll
            for (int pi = 0; pi < 4; pi++) {
                fma2(acc[qi][pi], a[qi].x, p[pi].x);
                fma2(acc[qi][pi], a[qi].y, p[pi].y);
            }
    }
}

__global__ __launch_bounds__(256, 2) void corr_kernel(const float* __restrict__ f1,
                                                      const float* __restrict__ cen,
                                                      float* __restrict__ out) {
    extern __shared__ float sm[];
    float* Ps = sm;                           // 169*132
    float* As = sm + NPOS_MAX * PSTRH;        // 16*132
    float* Ds = As + 16 * PSTRH;              // 16*172
    __shared__ __align__(8) unsigned long long mbar_s;

    int blk = blockIdx.x;
    int lvl = blk & 3, bin = blk >> 2;
    int b = bin >> 8, by = (bin >> 4) & 15, bx = bin & 15;
    int nq = g_cnt[bin]; if (nq > QCAP) nq = QCAP;
    if (nq == 0) return;

    int ixmin = (4 * bx) >> lvl, ixmax = (4 * bx + 3) >> lvl;
    int iymin = (4 * by) >> lvl, iymax = (4 * by + 3) >> lvl;
    int px0 = ixmin - 4, py0 = iymin - 4;
    int pw = ixmax - ixmin + 10, ph = iymax - iymin + 10;
    int Npos = pw * ph;
    int pwp = c_lvl_pw[lvl];

    int tid = threadIdx.x, lane = tid & 31, w = tid >> 5;
    int qsel = lane >> 3, psel = lane & 7;
    int wbase = w * 32;
    float scale = 1.0f / (float)(1 << lvl);

    unsigned Ps_b = (unsigned)__cvta_generic_to_shared(Ps);
    unsigned As_b = (unsigned)__cvta_generic_to_shared(As);
    unsigned mbar = (unsigned)__cvta_generic_to_shared(&mbar_s);

    if (tid == 0) mbar_init(mbar, 1);
    __syncthreads();
    unsigned par = 0;

    int pidx[4];
    #pragma unroll
    for (int pi = 0; pi < 4; pi++) {
        int p = wbase + psel + 8 * pi;
        pidx[pi] = (p < Npos) ? p : (Npos - 1);
    }

    for (int q0 = 0; q0 < nq; q0 += 16) {
        int qcnt = nq - q0; if (qcnt > 16) qcnt = 16;
        int nqi = (qcnt + 3) >> 2;            // 1..4, uniform across warps

        unsigned long long acc[4][4];
        #pragma unroll
        for (int qi = 0; qi < 4; qi++)
            #pragma unroll
            for (int pi = 0; pi < 4; pi++) acc[qi][pi] = 0ull;

        for (int h = 0; h < 2; h++) {
            __syncthreads();   // previous phase's smem fully consumed
            if (tid == 0) mbar_expect(mbar, (unsigned)(Npos + 16) * 512u);

            const float* pbase = g_pyr2
                + ((size_t)(b * 2 + h) * TOTPOS + c_lvl_base[lvl]
                   + (size_t)(py0 + 4) * pwp + (px0 + 4)) * 128;
            int nops = Npos + 16;
            for (int i = tid; i < nops; i += 256) {
                if (i < Npos) {
                    int ly = i / pw, lx = i - (i / pw) * pw;
                    bulkcp(Ps_b + (unsigned)(i * PSTRH) * 4u,
                           pbase + ((size_t)ly * pwp + lx) * 128, 512u, mbar);
                } else {
                    int qq = i - Npos;
                    int qv = (qq < qcnt) ? qq : 0;
                    int m = g_qlist[bin * QCAP + q0 + qv];
                    bulkcp(As_b + (unsigned)(qq * PSTRH) * 4u,
                           f1 + ((size_t)b * MM + m) * CC + h * 128, 512u, mbar);
                }
            }
            mbar_wait(mbar, par);
            par ^= 1;

            if (wbase < Npos) {
                switch (nqi) {
                    case 4: gemm_half<4>(As, Ps, qsel, pidx, acc); break;
                    case 3: gemm_half<3>(As, Ps, qsel, pidx, acc); break;
                    case 2: gemm_half<2>(As, Ps, qsel, pidx, acc); break;
                    default: gemm_half<1>(As, Ps, qsel, pidx, acc); break;
                }
            }
        }

        // ---- write D -------------------------------------------------------
        if (wbase < Npos) {
            #pragma unroll
            for (int qi = 0; qi < 4; qi++)
                #pragma unroll
                for (int pi = 0; pi < 4; pi++) {
                    int p = wbase + psel + 8 * pi;
                    if (p < Npos)
                        Ds[(qsel + 4 * qi) * DSTR + p] = unpack_sum(acc[qi][pi]);
                }
        }
        __syncthreads();

        // ---- bilinear epilogue: warp per query -----------------------------
        for (int qq = w; qq < qcnt; qq += 8) {
            int m = g_qlist[bin * QCAP + q0 + qq];
            float cx = cen[((size_t)b * MM + m) * 2 + 0];
            float cy = cen[((size_t)b * MM + m) * 2 + 1];
            float sx = cx * scale, sy = cy * scale;
            float fix = floorf(sx), fiy = floorf(sy);
            float fx = sx - fix, fy = sy - fiy;
            int ox = (int)fix - 4 - px0;
            int oy = (int)fiy - 4 - py0;
            float wx1 = fx, wx0 = 1.f - fx, wy1 = fy, wy0 = 1.f - fy;
            const float* Dq = Ds + qq * DSTR;
            for (int e = lane; e < 81; e += 32) {
                int i = e / 9, j = e - (e / 9) * 9;
                int base = (oy + j) * pw + (ox + i);
                float d00 = Dq[base],      d01 = Dq[base + 1];
                float d10 = Dq[base + pw], d11 = Dq[base + pw + 1];
                float val = wy0 * (wx0 * d00 + wx1 * d01)
                          + wy1 * (wx0 * d10 + wx1 * d11);
                out[((size_t)b * 324 + lvl * 81 + e) * MM + m] = val;
            }
        }
    }
}

// ---------------- launch ----------------------------------------------------
extern "C" void kernel_launch(void* const* d_in, const int* in_sizes, int n_in,
                              void* d_out, int out_size) {
    const float* f1  = (const float*)d_in[0];
    const float* f2  = (const float*)d_in[1];
    const float* cen = (const float*)d_in[2];
    float* out = (float*)d_out;

    size_t smem = (size_t)(NPOS_MAX * PSTRH + 16 * PSTRH + 16 * DSTR) * sizeof(float);
    cudaFuncSetAttribute(corr_kernel, cudaFuncAttributeMaxDynamicSharedMemorySize,
                         (int)smem);

    transpose_kernel<<<dim3(HW * HW / 32, CC / 32, BB), dim3(32, 32)>>>(f2);
    pool_all_kernel<<<BB * 1344, 256>>>();
    hist_kernel<<<32, 256>>>(cen);
    corr_kernel<<<NBINS * 4, 256, smem>>>(f1, cen, out);
}